// round 16
// baseline (speedup 1.0000x reference)
#include <cuda_runtime.h>
#include <cuda_fp16.h>
#include <cstdint>

#define D_MODEL 1024
#define N_HEADS 16
#define D_K     64
#define B_      2
#define S_      2048
#define M_TOT   (B_ * S_)
#define BH_     (B_ * N_HEADS)

// ---------------------------------------------------------------------------
// Scratch: everything hi-only fp16 (pure fp16 pipeline, RN quantization).
// ---------------------------------------------------------------------------
__device__ __half g_xh[(size_t)M_TOT * D_MODEL];
__device__ __half g_Wh[4][(size_t)D_MODEL * D_MODEL];
__device__ __half g_Qh[(size_t)BH_ * S_ * D_K];
__device__ __half g_Kh[(size_t)BH_ * S_ * D_K];
__device__ __half g_Vh[(size_t)BH_ * S_ * D_K];
__device__ __half g_Oh[(size_t)BH_ * S_ * D_K];

__device__ __forceinline__ uint32_t smem_u32(const void* p) {
    uint32_t a;
    asm("{ .reg .u64 t; cvta.to.shared.u64 t, %1; cvt.u32.u64 %0, t; }"
        : "=r"(a) : "l"(p));
    return a;
}

#define MMA16(d, a, b0, b1)                                                  \
    asm volatile(                                                            \
        "mma.sync.aligned.m16n8k16.row.col.f32.f16.f16.f32 "                 \
        "{%0,%1,%2,%3}, {%4,%5,%6,%7}, {%8,%9}, {%0,%1,%2,%3};"              \
        : "+f"((d)[0]), "+f"((d)[1]), "+f"((d)[2]), "+f"((d)[3])             \
        : "r"((a)[0]), "r"((a)[1]), "r"((a)[2]), "r"((a)[3]),                \
          "r"(b0), "r"(b1))

#define LDSM4(r0, r1, r2, r3, a)                                             \
    asm volatile("ldmatrix.sync.aligned.m8n8.x4.shared.b16 {%0,%1,%2,%3}, [%4];" \
        : "=r"(r0), "=r"(r1), "=r"(r2), "=r"(r3) : "r"(a))
#define LDSM4T(r0, r1, r2, r3, a)                                            \
    asm volatile("ldmatrix.sync.aligned.m8n8.x4.trans.shared.b16 {%0,%1,%2,%3}, [%4];" \
        : "=r"(r0), "=r"(r1), "=r"(r2), "=r"(r3) : "r"(a))

#define CPA16(saddr, gptr)                                                   \
    asm volatile("cp.async.ca.shared.global [%0], [%1], 16;"                 \
                 :: "r"(saddr), "l"(gptr))
#define CPA_COMMIT() asm volatile("cp.async.commit_group;" ::: "memory")
#define CPA_WAIT0()  asm volatile("cp.async.wait_group 0;" ::: "memory")
#define CPA_WAIT1()  asm volatile("cp.async.wait_group 1;" ::: "memory")

__device__ __forceinline__ uint32_t packh2(float a, float b) {
    __half2 h = __floats2half2_rn(a, b);
    return *(uint32_t*)&h;
}

// ---------------------------------------------------------------------------
// Split: fp32 -> fp16 (RN). Grid 8192: [0,4096)=x, rest W.
// ---------------------------------------------------------------------------
__global__ void __launch_bounds__(256) split_all(
    const float4* __restrict__ x,  const float4* __restrict__ w0,
    const float4* __restrict__ w1, const float4* __restrict__ w2,
    const float4* __restrict__ w3)
{
    const int bi = blockIdx.x;
    const float4* src; __half2* hi; int i;
    if (bi < 4096) {
        src = x; hi = (__half2*)g_xh;
        i = bi * 256 + threadIdx.x;
    } else {
        const int w = (bi - 4096) >> 10;
        const float4* ws[4] = {w0, w1, w2, w3};
        src = ws[w]; hi = (__half2*)g_Wh[w];
        i = ((bi - 4096) & 1023) * 256 + threadIdx.x;
    }
    float4 v = src[i];
    hi[i * 2]     = __floats2half2_rn(v.x, v.y);
    hi[i * 2 + 1] = __floats2half2_rn(v.z, v.w);
}

// ---------------------------------------------------------------------------
// Pure fp16 GEMM: C = Ah @ Wh^T + bias. BK=64, 3-stage cp.async ring
// (wait_group 1, exactly 2 groups pending; chunk c -> stage c%3, prefetch
// c+2 -> stage (c+2)%3, disjoint from the stage being read).
// Stride 36 words (32 data + 4 pad -> conflict-free LDSM). 16 iterations,
// 1 barrier + 64 MMAs/warp each. Smem 3 x 36864 B = 110592 B, 2 CTAs/SM.
// mode 0: fused QKV grid (24,32), hi-only fp16 outputs (Q folds x0.125).
// mode 1: out-proj grid (8,32), A = g_Oh, fp32 out.
// ---------------------------------------------------------------------------
#define GSTR  36                    // words per row (64 halves + 8 pad)
#define GTILE (128 * GSTR)          // 4608 words per tile
#define GSTAGE (2 * GTILE)          // Ah + Bh per stage
#define GEMM_SMEM (3 * GSTAGE * 4)  // 110592 B

__global__ void __launch_bounds__(256, 2) gemm_f16(
    const float* __restrict__ b0p, const float* __restrict__ b1p,
    const float* __restrict__ b2p, float* __restrict__ outp, int mode)
{
    extern __shared__ uint32_t smv[];
    const int tid = threadIdx.x;
    const int wid = tid >> 5, lane = tid & 31;
    const int g   = lane >> 2, tig = lane & 3;
    const int wm  = (wid >> 2) * 64;
    const int wn  = (wid & 3) * 32;
    const int bx = blockIdx.x;
    const int m0 = blockIdx.y * 128;
    const int target = mode ? 3 : (bx >> 3);
    const int n0 = (mode ? bx : (bx & 7)) * 128;

    const __half* Ah = mode ? g_Oh : g_xh;
    const __half* Wh = g_Wh[target];
    const float* bias = mode ? b0p
                             : (target == 0 ? b0p : target == 1 ? b1p : b2p);
    __half* oh = nullptr;
    if (target == 0)      oh = g_Qh;
    else if (target == 1) oh = g_Kh;
    else if (target == 2) oh = g_Vh;
    const bool hs = (mode == 0);
    const float sc = (mode == 0 && target == 0) ? 0.125f : 1.0f;

    const uint32_t sbase = smem_u32(smv);

    // loaders: group 0 -> Ah row lt, group 1 -> Bh row lt; 64 halves = 8x16B.
    const int gsel = tid >> 7, lt = tid & 127;
    const __half* sp = (gsel == 0 ? Ah + (size_t)(m0 + lt) * D_MODEL
                                  : Wh + (size_t)(n0 + lt) * D_MODEL);
    const uint32_t dst0 = sbase + (uint32_t)((gsel ? GTILE : 0) + lt * GSTR) * 4;

    auto load_chunk = [&](int kc) {
        const uint32_t bo = (uint32_t)(kc % 3) * GSTAGE * 4;
        const __half* s0 = sp + kc * 64;
        #pragma unroll
        for (int j = 0; j < 8; j++)
            CPA16(dst0 + bo + j * 16, s0 + j * 8);
        CPA_COMMIT();
    };

    float acc[4][4][4];
    #pragma unroll
    for (int i = 0; i < 4; i++)
        #pragma unroll
        for (int j = 0; j < 4; j++)
            acc[i][j][0] = acc[i][j][1] = acc[i][j][2] = acc[i][j][3] = 0.f;

    load_chunk(0);
    load_chunk(1);

    const uint32_t a_off = ((wm + (lane & 15)) * GSTR + ((lane >> 4) << 2)) * 4;
    const uint32_t b_off = ((wn + (lane & 7) + ((lane >> 4) << 3)) * GSTR
                            + (((lane >> 3) & 1) << 2)) * 4;

    for (int c = 0; c < 16; c++) {
        CPA_WAIT1();          // drains chunk c (2 groups always pending)
        __syncthreads();
        if (c + 2 < 16) load_chunk(c + 2);
        else            CPA_COMMIT();    // empty group keeps invariant

        const uint32_t Bb = sbase + (uint32_t)(c % 3) * GSTAGE * 4;
        #pragma unroll
        for (int st = 0; st < 4; st++) {
            uint32_t bh[4][2];
            #pragma unroll
            for (int p = 0; p < 2; p++) {
                const uint32_t ad = Bb + GTILE * 4 + b_off
                                    + (p * 16 * GSTR + st * 8) * 4;
                LDSM4(bh[2*p][0], bh[2*p][1], bh[2*p+1][0], bh[2*p+1][1], ad);
            }
            #pragma unroll
            for (int mb = 0; mb < 4; mb++) {
                uint32_t ah[4];
                const uint32_t ad = Bb + a_off + (mb * 16 * GSTR + st * 8) * 4;
                LDSM4(ah[0], ah[1], ah[2], ah[3], ad);
                #pragma unroll
                for (int nb = 0; nb < 4; nb++)
                    MMA16(acc[mb][nb], ah, bh[nb][0], bh[nb][1]);
            }
        }
    }

    #pragma unroll
    for (int nb = 0; nb < 4; nb++) {
        const int col = n0 + wn + nb * 8 + 2 * tig;
        const float b0 = bias[col], b1 = bias[col + 1];
        #pragma unroll
        for (int mb = 0; mb < 4; mb++) {
            const int row0 = m0 + wm + mb * 16 + g;
            #pragma unroll
            for (int hf = 0; hf < 2; hf++) {
                const int row = row0 + hf * 8;
                const float v0 = (acc[mb][nb][hf * 2]     + b0) * sc;
                const float v1 = (acc[mb][nb][hf * 2 + 1] + b1) * sc;
                if (hs) {
                    const int h = col >> 6, d0 = col & 63;
                    const int bb = row >> 11, ss = row & (S_ - 1);
                    *(__half2*)&oh[(((size_t)bb * N_HEADS + h) * S_ + ss) * D_K + d0] =
                        __floats2half2_rn(v0, v1);
                } else {
                    *(float2*)&outp[(size_t)row * D_MODEL + col] =
                        make_float2(v0, v1);
                }
            }
        }
    }
}

// ---------------------------------------------------------------------------
// Flash attention, FA2 layout (8 warps x 16 q-rows), pure 1-term fp16.
// Occupancy 1 (reverted: occ-2 regressed via register spills).
// Smem (words): Qh 0 (4608), per buf (stride 9216): Kh +0, Vh +4608.
// ---------------------------------------------------------------------------
#define OQH  0
#define OKV0 4608
#define PBUF 9216
#define ATT_SMEM ((OKV0 + 2 * PBUF) * 4)   // 92160 B

__global__ void __launch_bounds__(256, 1) attn_f16()
{
    extern __shared__ uint32_t smv[];
    const int tid  = threadIdx.x;
    const int wid  = tid >> 5, lane = tid & 31;
    const int g    = lane >> 2;
    const int tig  = lane & 3;
    const int wm   = wid * 16;
    const int q0 = blockIdx.x * 128;
    const int bhid = blockIdx.y;
    const size_t hb = (size_t)bhid * S_ * D_K;
    const uint32_t sbase = smem_u32(smv);

    // Q tile load: row = tid>>1, half = (tid&1)*32 halves.
    {
        const int row = tid >> 1, half = (tid & 1) * 32;
        const __half* src = g_Qh + hb + (size_t)(q0 + row) * D_K + half;
        uint32_t* dst = smv + OQH + row * 36 + half / 2;
        #pragma unroll
        for (int s2 = 0; s2 < 4; s2++)
            *(uint4*)(dst + s2 * 4) = *(const uint4*)(src + s2 * 8);
    }

    // K/V cp.async loader: group 0 -> Kh row lt, group 1 -> Vh row lt.
    const int gsel = tid >> 7, lt = tid & 127;
    const __half* kvsrc = (gsel == 0 ? g_Kh : g_Vh) + hb + (size_t)lt * D_K;
    const uint32_t kvoff = (uint32_t)((gsel ? 4608 : 0) + lt * 36) * 4;

    auto load_tile = [&](int tt, int buf) {
        const uint32_t base = sbase + (OKV0 + buf * PBUF) * 4;
        const __half* s0 = kvsrc + (size_t)tt * 128 * D_K;
        #pragma unroll
        for (int j = 0; j < 8; j++)
            CPA16(base + kvoff + j * 16, s0 + j * 8);
        CPA_COMMIT();
    };

    load_tile(0, 0);
    __syncthreads();   // Q smem visible

    // Q fragments resident in registers.
    uint32_t qh[4][4];
    {
        const uint32_t qa_off = ((wm + (lane & 15)) * 36
                                 + ((lane >> 4) << 2)) * 4;
        #pragma unroll
        for (int st = 0; st < 4; st++) {
            const uint32_t ad = sbase + qa_off + (st * 8) * 4;
            LDSM4(qh[st][0], qh[st][1], qh[st][2], qh[st][3], ad);
        }
    }

    const uint32_t kb_off = (((lane & 7) + ((lane >> 4) << 3)) * 36
                             + (((lane >> 3) & 1) << 2)) * 4;
    const uint32_t vb_off = (((lane & 7) + (((lane >> 3) & 1) << 3)) * 36
                             + ((lane >> 4) << 2)) * 4;

    float m_r[2] = {-1e30f, -1e30f}, l_r[2] = {0.f, 0.f};
    float o_acc[8][4];
    #pragma unroll
    for (int nb = 0; nb < 8; nb++)
        o_acc[nb][0] = o_acc[nb][1] = o_acc[nb][2] = o_acc[nb][3] = 0.f;

    for (int t = 0; t < S_ / 128; t++) {
        const int buf = t & 1;
        CPA_WAIT0();
        __syncthreads();

        // ---- S = Qh Kh^T ----
        float s_acc[16][4];
        #pragma unroll
        for (int nb = 0; nb < 16; nb++)
            s_acc[nb][0] = s_acc[nb][1] = s_acc[nb][2] = s_acc[nb][3] = 0.f;

        const uint32_t kB = sbase + (OKV0 + buf * PBUF) * 4;
        #pragma unroll
        for (int st = 0; st < 4; st++) {
            #pragma unroll
            for (int p = 0; p < 8; p++) {
                uint32_t bh[4];
                const uint32_t ad = kB + kb_off + (p * 16 * 36 + st * 8) * 4;
                LDSM4(bh[0], bh[1], bh[2], bh[3], ad);
                MMA16(s_acc[2*p],   qh[st], bh[0], bh[1]);
                MMA16(s_acc[2*p+1], qh[st], bh[2], bh[3]);
            }
        }

        if (t + 1 < S_ / 128) load_tile(t + 1, buf ^ 1);

        // ---- warp-local online softmax (rows g and g+8) ----
        float mx0 = -1e30f, mx1 = -1e30f;
        #pragma unroll
        for (int nb = 0; nb < 16; nb++) {
            mx0 = fmaxf(mx0, fmaxf(s_acc[nb][0], s_acc[nb][1]));
            mx1 = fmaxf(mx1, fmaxf(s_acc[nb][2], s_acc[nb][3]));
        }
        mx0 = fmaxf(mx0, __shfl_xor_sync(0xffffffffu, mx0, 1));
        mx0 = fmaxf(mx0, __shfl_xor_sync(0xffffffffu, mx0, 2));
        mx1 = fmaxf(mx1, __shfl_xor_sync(0xffffffffu, mx1, 1));
        mx1 = fmaxf(mx1, __shfl_xor_sync(0xffffffffu, mx1, 2));

        const float mn0 = fmaxf(m_r[0], mx0), mn1 = fmaxf(m_r[1], mx1);
        const float c0 = __expf(m_r[0] - mn0), c1 = __expf(m_r[1] - mn1);
        m_r[0] = mn0; m_r[1] = mn1;

        float sum0 = 0.f, sum1 = 0.f;
        #pragma unroll
        for (int nb = 0; nb < 16; nb++) {
            float p0 = __expf(s_acc[nb][0] - mn0);
            float p1 = __expf(s_acc[nb][1] - mn0);
            float p2 = __expf(s_acc[nb][2] - mn1);
            float p3 = __expf(s_acc[nb][3] - mn1);
            s_acc[nb][0] = p0; s_acc[nb][1] = p1;
            s_acc[nb][2] = p2; s_acc[nb][3] = p3;
            sum0 += p0 + p1; sum1 += p2 + p3;
        }
        sum0 += __shfl_xor_sync(0xffffffffu, sum0, 1);
        sum0 += __shfl_xor_sync(0xffffffffu, sum0, 2);
        sum1 += __shfl_xor_sync(0xffffffffu, sum1, 1);
        sum1 += __shfl_xor_sync(0xffffffffu, sum1, 2);
        l_r[0] = l_r[0] * c0 + sum0;
        l_r[1] = l_r[1] * c1 + sum1;

        #pragma unroll
        for (int nb = 0; nb < 8; nb++) {
            o_acc[nb][0] *= c0; o_acc[nb][1] *= c0;
            o_acc[nb][2] *= c1; o_acc[nb][3] *= c1;
        }

        // ---- O += P Vh; P C-frags -> A-frags in registers ----
        const uint32_t vB = sbase + (OKV0 + buf * PBUF + 4608) * 4;
        #pragma unroll
        for (int kk = 0; kk < 8; kk++) {
            uint32_t pa[4];
            pa[0] = packh2(s_acc[2*kk][0],   s_acc[2*kk][1]);
            pa[1] = packh2(s_acc[2*kk][2],   s_acc[2*kk][3]);
            pa[2] = packh2(s_acc[2*kk+1][0], s_acc[2*kk+1][1]);
            pa[3] = packh2(s_acc[2*kk+1][2], s_acc[2*kk+1][3]);
            #pragma unroll
            for (int dp = 0; dp < 4; dp++) {
                uint32_t vh[4];
                const uint32_t vad = vB + vb_off + (kk * 16 * 36 + dp * 8) * 4;
                LDSM4T(vh[0], vh[1], vh[2], vh[3], vad);
                MMA16(o_acc[2*dp],   pa, vh[0], vh[1]);
                MMA16(o_acc[2*dp+1], pa, vh[2], vh[3]);
            }
        }
    }

    // ---- epilogue: normalize, write hi-only O [B,S,H,64] ----
    const int b = bhid >> 4, h = bhid & 15;
    const float inv0 = 1.0f / l_r[0], inv1 = 1.0f / l_r[1];
    const int qrow = q0 + wm + g;
    #pragma unroll
    for (int nb = 0; nb < 8; nb++) {
        const int col = nb * 8 + 2 * tig;
        *(__half2*)&g_Oh[(((size_t)b * S_ + qrow) * N_HEADS + h) * D_K + col] =
            __floats2half2_rn(o_acc[nb][0] * inv0, o_acc[nb][1] * inv0);
        *(__half2*)&g_Oh[(((size_t)b * S_ + qrow + 8) * N_HEADS + h) * D_K + col] =
            __floats2half2_rn(o_acc[nb][2] * inv1, o_acc[nb][3] * inv1);
    }
}

// ---------------------------------------------------------------------------
extern "C" void kernel_launch(void* const* d_in, const int* in_sizes, int n_in,
                              void* d_out, int out_size)
{
    const float* x  = (const float*)d_in[0];
    const float* Wq = (const float*)d_in[1];
    const float* bq = (const float*)d_in[2];
    const float* Wk = (const float*)d_in[3];
    const float* bk = (const float*)d_in[4];
    const float* Wv = (const float*)d_in[5];
    const float* bv = (const float*)d_in[6];
    const float* Wo = (const float*)d_in[7];
    const float* bo = (const float*)d_in[8];
    float* out = (float*)d_out;

    cudaFuncSetAttribute(gemm_f16, cudaFuncAttributeMaxDynamicSharedMemorySize,
                         GEMM_SMEM);
    cudaFuncSetAttribute(attn_f16, cudaFuncAttributeMaxDynamicSharedMemorySize,
                         ATT_SMEM);

    split_all<<<8192, 256>>>((const float4*)x, (const float4*)Wq,
                             (const float4*)Wk, (const float4*)Wv,
                             (const float4*)Wo);

    gemm_f16<<<dim3(24, M_TOT / 128), 256, GEMM_SMEM>>>(bq, bk, bv, nullptr, 0);

    attn_f16<<<dim3(S_ / 128, BH_), 256, ATT_SMEM>>>();

    gemm_f16<<<dim3(8, M_TOT / 128), 256, GEMM_SMEM>>>(bo, nullptr, nullptr, out, 1);
}

// round 17
// speedup vs baseline: 1.7157x; 1.7157x over previous
#include <cuda_runtime.h>
#include <cuda_fp16.h>
#include <cstdint>

#define D_MODEL 1024
#define N_HEADS 16
#define D_K     64
#define B_      2
#define S_      2048
#define M_TOT   (B_ * S_)
#define BH_     (B_ * N_HEADS)

// ---------------------------------------------------------------------------
// Scratch: everything hi-only fp16 (pure fp16 pipeline, RN quantization).
// ---------------------------------------------------------------------------
__device__ __half g_xh[(size_t)M_TOT * D_MODEL];
__device__ __half g_Wh[4][(size_t)D_MODEL * D_MODEL];
__device__ __half g_Qh[(size_t)BH_ * S_ * D_K];
__device__ __half g_Kh[(size_t)BH_ * S_ * D_K];
__device__ __half g_Vh[(size_t)BH_ * S_ * D_K];
__device__ __half g_Oh[(size_t)BH_ * S_ * D_K];

__device__ __forceinline__ uint32_t smem_u32(const void* p) {
    uint32_t a;
    asm("{ .reg .u64 t; cvta.to.shared.u64 t, %1; cvt.u32.u64 %0, t; }"
        : "=r"(a) : "l"(p));
    return a;
}

#define MMA16(d, a, b0, b1)                                                  \
    asm volatile(                                                            \
        "mma.sync.aligned.m16n8k16.row.col.f32.f16.f16.f32 "                 \
        "{%0,%1,%2,%3}, {%4,%5,%6,%7}, {%8,%9}, {%0,%1,%2,%3};"              \
        : "+f"((d)[0]), "+f"((d)[1]), "+f"((d)[2]), "+f"((d)[3])             \
        : "r"((a)[0]), "r"((a)[1]), "r"((a)[2]), "r"((a)[3]),                \
          "r"(b0), "r"(b1))

#define LDSM4(r0, r1, r2, r3, a)                                             \
    asm volatile("ldmatrix.sync.aligned.m8n8.x4.shared.b16 {%0,%1,%2,%3}, [%4];" \
        : "=r"(r0), "=r"(r1), "=r"(r2), "=r"(r3) : "r"(a))
#define LDSM4T(r0, r1, r2, r3, a)                                            \
    asm volatile("ldmatrix.sync.aligned.m8n8.x4.trans.shared.b16 {%0,%1,%2,%3}, [%4];" \
        : "=r"(r0), "=r"(r1), "=r"(r2), "=r"(r3) : "r"(a))

#define CPA16(saddr, gptr)                                                   \
    asm volatile("cp.async.ca.shared.global [%0], [%1], 16;"                 \
                 :: "r"(saddr), "l"(gptr))
#define CPA_COMMIT() asm volatile("cp.async.commit_group;" ::: "memory")
#define CPA_WAIT0()  asm volatile("cp.async.wait_group 0;" ::: "memory")
#define CPA_WAIT2()  asm volatile("cp.async.wait_group 2;" ::: "memory")

__device__ __forceinline__ uint32_t packh2(float a, float b) {
    __half2 h = __floats2half2_rn(a, b);
    return *(uint32_t*)&h;
}

// ---------------------------------------------------------------------------
// Split: fp32 -> fp16 (RN). Grid 8192: [0,4096)=x, rest W.
// ---------------------------------------------------------------------------
__global__ void __launch_bounds__(256) split_all(
    const float4* __restrict__ x,  const float4* __restrict__ w0,
    const float4* __restrict__ w1, const float4* __restrict__ w2,
    const float4* __restrict__ w3)
{
    const int bi = blockIdx.x;
    const float4* src; __half2* hi; int i;
    if (bi < 4096) {
        src = x; hi = (__half2*)g_xh;
        i = bi * 256 + threadIdx.x;
    } else {
        const int w = (bi - 4096) >> 10;
        const float4* ws[4] = {w0, w1, w2, w3};
        src = ws[w]; hi = (__half2*)g_Wh[w];
        i = ((bi - 4096) & 1023) * 256 + threadIdx.x;
    }
    float4 v = src[i];
    hi[i * 2]     = __floats2half2_rn(v.x, v.y);
    hi[i * 2 + 1] = __floats2half2_rn(v.z, v.w);
}

// ---------------------------------------------------------------------------
// Pure fp16 GEMM: C = Ah @ Wh^T + bias. BK=32, 4-stage cp.async pipeline
// (wait_group 2; empty commits in tail). COALESCED loader: lane-major chunk
// index c = i*128 + lt -> (row c>>2, 16B chunk c&3); a warp instruction
// covers 8 rows x contiguous 64 B instead of 32 scattered lines.
// Smem per stage: Ah(0), Bh(GTILE); stride 20 words. 4 stages = 80 KB.
// mode 0: fused QKV grid (24,32), hi-only fp16 out (Q folds x0.125).
// mode 1: out-proj grid (8,32), A = g_Oh, fp32 out.
// ---------------------------------------------------------------------------
#define GSTR  20
#define GTILE (128 * GSTR)
#define GBUF  (2 * GTILE)
#define GEMM_SMEM (4 * GBUF * 4)  // 81920 B

__global__ void __launch_bounds__(256, 2) gemm_f16(
    const float* __restrict__ b0p, const float* __restrict__ b1p,
    const float* __restrict__ b2p, float* __restrict__ outp, int mode)
{
    extern __shared__ uint32_t smv[];
    const int tid = threadIdx.x;
    const int wid = tid >> 5, lane = tid & 31;
    const int g   = lane >> 2, tig = lane & 3;
    const int wm  = (wid >> 2) * 64;
    const int wn  = (wid & 3) * 32;
    const int bx = blockIdx.x;
    const int m0 = blockIdx.y * 128;
    const int target = mode ? 3 : (bx >> 3);
    const int n0 = (mode ? bx : (bx & 7)) * 128;

    const __half* Ah = mode ? g_Oh : g_xh;
    const __half* Wh = g_Wh[target];
    const float* bias = mode ? b0p
                             : (target == 0 ? b0p : target == 1 ? b1p : b2p);
    __half* oh = nullptr;
    if (target == 0)      oh = g_Qh;
    else if (target == 1) oh = g_Kh;
    else if (target == 2) oh = g_Vh;
    const bool hs = (mode == 0);
    const float sc = (mode == 0 && target == 0) ? 0.125f : 1.0f;

    const uint32_t sbase = smem_u32(smv);

    // Coalesced loader: group 0 -> Ah tile, group 1 -> Bh tile.
    // 512 16B-chunks per tile; thread lt takes c = i*128 + lt, i = 0..3.
    const int gsel = tid >> 7, lt = tid & 127;
    const __half* gbase = (gsel == 0 ? Ah + (size_t)m0 * D_MODEL
                                     : Wh + (size_t)n0 * D_MODEL);
    const uint32_t tbase = sbase + (uint32_t)(gsel ? GTILE : 0) * 4;
    // per-i row/chunk precomputed
    int lrow[4]; uint32_t ldst[4]; const __half* lsrc[4];
    #pragma unroll
    for (int i = 0; i < 4; i++) {
        const int c = i * 128 + lt;
        const int row = c >> 2, j = c & 3;
        lrow[i] = row;
        lsrc[i] = gbase + (size_t)row * D_MODEL + j * 8;
        ldst[i] = tbase + (uint32_t)(row * GSTR + j * 4) * 4;
    }

    auto load_chunk = [&](int kc) {
        const uint32_t bo = (kc & 3) * GBUF * 4;
        #pragma unroll
        for (int i = 0; i < 4; i++)
            CPA16(ldst[i] + bo, lsrc[i] + kc * 32);
        CPA_COMMIT();
    };

    float acc[4][4][4];
    #pragma unroll
    for (int i = 0; i < 4; i++)
        #pragma unroll
        for (int j = 0; j < 4; j++)
            acc[i][j][0] = acc[i][j][1] = acc[i][j][2] = acc[i][j][3] = 0.f;

    load_chunk(0);
    load_chunk(1);
    load_chunk(2);

    const uint32_t a_off = ((wm + (lane & 15)) * GSTR + ((lane >> 4) << 2)) * 4;
    const uint32_t b_off = ((wn + (lane & 7) + ((lane >> 4) << 3)) * GSTR
                            + (((lane >> 3) & 1) << 2)) * 4;

    for (int c = 0; c < 32; c++) {
        CPA_WAIT2();          // drains chunk c (3 groups always pending)
        __syncthreads();
        if (c + 3 < 32) load_chunk(c + 3);
        else            CPA_COMMIT();   // empty group keeps invariant

        const uint32_t Bb = sbase + (c & 3) * GBUF * 4;
        #pragma unroll
        for (int st = 0; st < 2; st++) {
            uint32_t bh[4][2];
            #pragma unroll
            for (int p = 0; p < 2; p++) {
                const uint32_t ad = Bb + GTILE * 4 + b_off
                                    + (p * 16 * GSTR + st * 8) * 4;
                LDSM4(bh[2*p][0], bh[2*p][1], bh[2*p+1][0], bh[2*p+1][1], ad);
            }
            #pragma unroll
            for (int mb = 0; mb < 4; mb++) {
                uint32_t ah[4];
                const uint32_t ad = Bb + a_off + (mb * 16 * GSTR + st * 8) * 4;
                LDSM4(ah[0], ah[1], ah[2], ah[3], ad);
                #pragma unroll
                for (int nb = 0; nb < 4; nb++)
                    MMA16(acc[mb][nb], ah, bh[nb][0], bh[nb][1]);
            }
        }
    }

    #pragma unroll
    for (int nb = 0; nb < 4; nb++) {
        const int col = n0 + wn + nb * 8 + 2 * tig;
        const float b0 = bias[col], b1 = bias[col + 1];
        #pragma unroll
        for (int mb = 0; mb < 4; mb++) {
            const int row0 = m0 + wm + mb * 16 + g;
            #pragma unroll
            for (int hf = 0; hf < 2; hf++) {
                const int row = row0 + hf * 8;
                const float v0 = (acc[mb][nb][hf * 2]     + b0) * sc;
                const float v1 = (acc[mb][nb][hf * 2 + 1] + b1) * sc;
                if (hs) {
                    const int h = col >> 6, d0 = col & 63;
                    const int bb = row >> 11, ss = row & (S_ - 1);
                    *(__half2*)&oh[(((size_t)bb * N_HEADS + h) * S_ + ss) * D_K + d0] =
                        __floats2half2_rn(v0, v1);
                } else {
                    *(float2*)&outp[(size_t)row * D_MODEL + col] =
                        make_float2(v0, v1);
                }
            }
        }
    }
}

// ---------------------------------------------------------------------------
// Flash attention, FA2 layout (8 warps x 16 q-rows), pure 1-term fp16,
// occupancy 1 (measured best). COALESCED K/V loader: c = i*128 + lt ->
// (row c>>3, chunk c&7); warp covers 4 rows x contiguous 128 B.
// Smem (words): Qh 0 (4608), per buf (stride 9216): Kh +0, Vh +4608.
// ---------------------------------------------------------------------------
#define OQH  0
#define OKV0 4608
#define PBUF 9216
#define ATT_SMEM ((OKV0 + 2 * PBUF) * 4)   // 92160 B

__global__ void __launch_bounds__(256, 1) attn_f16()
{
    extern __shared__ uint32_t smv[];
    const int tid  = threadIdx.x;
    const int wid  = tid >> 5, lane = tid & 31;
    const int g    = lane >> 2;
    const int tig  = lane & 3;
    const int wm   = wid * 16;
    const int q0 = blockIdx.x * 128;
    const int bhid = blockIdx.y;
    const size_t hb = (size_t)bhid * S_ * D_K;
    const uint32_t sbase = smem_u32(smv);

    // Q tile load: row = tid>>1, half = (tid&1)*32 halves.
    {
        const int row = tid >> 1, half = (tid & 1) * 32;
        const __half* src = g_Qh + hb + (size_t)(q0 + row) * D_K + half;
        uint32_t* dst = smv + OQH + row * 36 + half / 2;
        #pragma unroll
        for (int s2 = 0; s2 < 4; s2++)
            *(uint4*)(dst + s2 * 4) = *(const uint4*)(src + s2 * 8);
    }

    // Coalesced K/V loader: group 0 -> Kh, group 1 -> Vh.
    // 1024 16B-chunks per tile; thread lt takes c = i*128 + lt, i = 0..7.
    const int gsel = tid >> 7, lt = tid & 127;
    const __half* kvb = (gsel == 0 ? g_Kh : g_Vh) + hb;
    const uint32_t kvt = (uint32_t)(gsel ? 4608 : 0);
    int krow[8]; uint32_t kdst[8]; const __half* ksrc[8];
    #pragma unroll
    for (int i = 0; i < 8; i++) {
        const int c = i * 128 + lt;
        const int row = c >> 3, j = c & 7;
        krow[i] = row;
        ksrc[i] = kvb + (size_t)row * D_K + j * 8;
        kdst[i] = sbase + (kvt + (uint32_t)(row * 36 + j * 4)) * 4;
    }

    auto load_tile = [&](int tt, int buf) {
        const uint32_t bo = (OKV0 + buf * PBUF) * 4;
        const size_t go = (size_t)tt * 128 * D_K;
        #pragma unroll
        for (int i = 0; i < 8; i++)
            CPA16(kdst[i] + bo, ksrc[i] + go);
        CPA_COMMIT();
    };

    load_tile(0, 0);
    __syncthreads();   // Q smem visible

    // Q fragments resident in registers.
    uint32_t qh[4][4];
    {
        const uint32_t qa_off = ((wm + (lane & 15)) * 36
                                 + ((lane >> 4) << 2)) * 4;
        #pragma unroll
        for (int st = 0; st < 4; st++) {
            const uint32_t ad = sbase + qa_off + (st * 8) * 4;
            LDSM4(qh[st][0], qh[st][1], qh[st][2], qh[st][3], ad);
        }
    }

    const uint32_t kb_off = (((lane & 7) + ((lane >> 4) << 3)) * 36
                             + (((lane >> 3) & 1) << 2)) * 4;
    const uint32_t vb_off = (((lane & 7) + (((lane >> 3) & 1) << 3)) * 36
                             + ((lane >> 4) << 2)) * 4;

    float m_r[2] = {-1e30f, -1e30f}, l_r[2] = {0.f, 0.f};
    float o_acc[8][4];
    #pragma unroll
    for (int nb = 0; nb < 8; nb++)
        o_acc[nb][0] = o_acc[nb][1] = o_acc[nb][2] = o_acc[nb][3] = 0.f;

    for (int t = 0; t < S_ / 128; t++) {
        const int buf = t & 1;
        CPA_WAIT0();
        __syncthreads();

        // ---- S = Qh Kh^T ----
        float s_acc[16][4];
        #pragma unroll
        for (int nb = 0; nb < 16; nb++)
            s_acc[nb][0] = s_acc[nb][1] = s_acc[nb][2] = s_acc[nb][3] = 0.f;

        const uint32_t kB = sbase + (OKV0 + buf * PBUF) * 4;
        #pragma unroll
        for (int st = 0; st < 4; st++) {
            #pragma unroll
            for (int p = 0; p < 8; p++) {
                uint32_t bh[4];
                const uint32_t ad = kB + kb_off + (p * 16 * 36 + st * 8) * 4;
                LDSM4(bh[0], bh[1], bh[2], bh[3], ad);
                MMA16(s_acc[2*p],   qh[st], bh[0], bh[1]);
                MMA16(s_acc[2*p+1], qh[st], bh[2], bh[3]);
            }
        }

        if (t + 1 < S_ / 128) load_tile(t + 1, buf ^ 1);

        // ---- warp-local online softmax (rows g and g+8) ----
        float mx0 = -1e30f, mx1 = -1e30f;
        #pragma unroll
        for (int nb = 0; nb < 16; nb++) {
            mx0 = fmaxf(mx0, fmaxf(s_acc[nb][0], s_acc[nb][1]));
            mx1 = fmaxf(mx1, fmaxf(s_acc[nb][2], s_acc[nb][3]));
        }
        mx0 = fmaxf(mx0, __shfl_xor_sync(0xffffffffu, mx0, 1));
        mx0 = fmaxf(mx0, __shfl_xor_sync(0xffffffffu, mx0, 2));
        mx1 = fmaxf(mx1, __shfl_xor_sync(0xffffffffu, mx1, 1));
        mx1 = fmaxf(mx1, __shfl_xor_sync(0xffffffffu, mx1, 2));

        const float mn0 = fmaxf(m_r[0], mx0), mn1 = fmaxf(m_r[1], mx1);
        const float c0 = __expf(m_r[0] - mn0), c1 = __expf(m_r[1] - mn1);
        m_r[0] = mn0; m_r[1] = mn1;

        float sum0 = 0.f, sum1 = 0.f;
        #pragma unroll
        for (int nb = 0; nb < 16; nb++) {
            float p0 = __expf(s_acc[nb][0] - mn0);
            float p1 = __expf(s_acc[nb][1] - mn0);
            float p2 = __expf(s_acc[nb][2] - mn1);
            float p3 = __expf(s_acc[nb][3] - mn1);
            s_acc[nb][0] = p0; s_acc[nb][1] = p1;
            s_acc[nb][2] = p2; s_acc[nb][3] = p3;
            sum0 += p0 + p1; sum1 += p2 + p3;
        }
        sum0 += __shfl_xor_sync(0xffffffffu, sum0, 1);
        sum0 += __shfl_xor_sync(0xffffffffu, sum0, 2);
        sum1 += __shfl_xor_sync(0xffffffffu, sum1, 1);
        sum1 += __shfl_xor_sync(0xffffffffu, sum1, 2);
        l_r[0] = l_r[0] * c0 + sum0;
        l_r[1] = l_r[1] * c1 + sum1;

        #pragma unroll
        for (int nb = 0; nb < 8; nb++) {
            o_acc[nb][0] *= c0; o_acc[nb][1] *= c0;
            o_acc[nb][2] *= c1; o_acc[nb][3] *= c1;
        }

        // ---- O += P Vh; P C-frags -> A-frags in registers ----
        const uint32_t vB = sbase + (OKV0 + buf * PBUF + 4608) * 4;
        #pragma unroll
        for (int kk = 0; kk < 8; kk++) {
            uint32_t pa[4];
            pa[0] = packh2(s_acc[2*kk][0],   s_acc[2*kk][1]);
            pa[1] = packh2(s_acc[2*kk][2],   s_acc[2*kk][3]);
            pa[2] = packh2(s_acc[2*kk+1][0], s_acc[2*kk+1][1]);
            pa[3] = packh2(s_acc[2*kk+1][2], s_acc[2*kk+1][3]);
            #pragma unroll
            for (int dp = 0; dp < 4; dp++) {
                uint32_t vh[4];
                const uint32_t vad = vB + vb_off + (kk * 16 * 36 + dp * 8) * 4;
                LDSM4T(vh[0], vh[1], vh[2], vh[3], vad);
                MMA16(o_acc[2*dp],   pa, vh[0], vh[1]);
                MMA16(o_acc[2*dp+1], pa, vh[2], vh[3]);
            }
        }
    }

    // ---- epilogue: normalize, write hi-only O [B,S,H,64] ----
    const int b = bhid >> 4, h = bhid & 15;
    const float inv0 = 1.0f / l_r[0], inv1 = 1.0f / l_r[1];
    const int qrow = q0 + wm + g;
    #pragma unroll
    for (int nb = 0; nb < 8; nb++) {
        const int col = nb * 8 + 2 * tig;
        *(__half2*)&g_Oh[(((size_t)b * S_ + qrow) * N_HEADS + h) * D_K + col] =
            __floats2half2_rn(o_acc[nb][0] * inv0, o_acc[nb][1] * inv0);
        *(__half2*)&g_Oh[(((size_t)b * S_ + qrow + 8) * N_HEADS + h) * D_K + col] =
            __floats2half2_rn(o_acc[nb][2] * inv1, o_acc[nb][3] * inv1);
    }
}

// ---------------------------------------------------------------------------
extern "C" void kernel_launch(void* const* d_in, const int* in_sizes, int n_in,
                              void* d_out, int out_size)
{
    const float* x  = (const float*)d_in[0];
    const float* Wq = (const float*)d_in[1];
    const float* bq = (const float*)d_in[2];
    const float* Wk = (const float*)d_in[3];
    const float* bk = (const float*)d_in[4];
    const float* Wv = (const float*)d_in[5];
    const float* bv = (const float*)d_in[6];
    const float* Wo = (const float*)d_in[7];
    const float* bo = (const float*)d_in[8];
    float* out = (float*)d_out;

    cudaFuncSetAttribute(gemm_f16, cudaFuncAttributeMaxDynamicSharedMemorySize,
                         GEMM_SMEM);
    cudaFuncSetAttribute(attn_f16, cudaFuncAttributeMaxDynamicSharedMemorySize,
                         ATT_SMEM);

    split_all<<<8192, 256>>>((const float4*)x, (const float4*)Wq,
                             (const float4*)Wk, (const float4*)Wv,
                             (const float4*)Wo);

    gemm_f16<<<dim3(24, M_TOT / 128), 256, GEMM_SMEM>>>(bq, bk, bv, nullptr, 0);

    attn_f16<<<dim3(S_ / 128, BH_), 256, ATT_SMEM>>>();

    gemm_f16<<<dim3(8, M_TOT / 128), 256, GEMM_SMEM>>>(bo, nullptr, nullptr, out, 1);
}